// round 9
// baseline (speedup 1.0000x reference)
#include <cuda_runtime.h>
#include <cuda_bf16.h>
#include <cstdint>

// ---------------- problem constants ----------------
#define V_REAL 50257
#define BN     128
#define NTILE  393                 // ceil(50257/128)
#define VPAD   (NTILE*BN)          // 50304
#define EDIM   512
#define MROWS  4096                // 4*1024
#define TOPK   8
#define NSEL   16                  // candidates rescored exactly
#define KEEP   8                   // per-tile top-8 kept
#define CAND   (NTILE*KEEP)        // 3144 candidates per row

// GEMM tiling
#define BM 128
#define BK 32
#define NKC (EDIM/BK)              // 16
#define LDA 40                     // bf16 elems, padded (80B rows, 16B aligned)
#define LDB 40

#define FLT_MAX_ 3.402823466e+38f
#define TINY_F   1.17549435e-38f   // FLT_MIN (jnp.finfo(f32).tiny)
#define NORM_EPS 1e-12f

// Dynamic smem: pipeline 40960B; epilogue reuses it as sc[128][66] = 33792B
#define SMEM_GEMM 40960

// ---------------- scratch (device globals; no allocation) ----------------
// Only referenced from device code (host-passing a __device__ symbol passes the
// host shadow address — the root bug of rounds 1-5).
static __device__ __nv_bfloat16 g_embn_bf16[(size_t)VPAD * EDIM];   // ~51.5 MB
static __device__ __nv_bfloat16 g_projn_bf16[(size_t)MROWS * EDIM]; // 4 MB
static __device__ float2        g_cand[(size_t)MROWS * CAND];       // ~103 MB

// ---------------- helpers ----------------
__device__ __forceinline__ void cp16(uint32_t dst, const void* src) {
    asm volatile("cp.async.cg.shared.global [%0], [%1], 16;\n" :: "r"(dst), "l"(src));
}
__device__ __forceinline__ void cp_commit() { asm volatile("cp.async.commit_group;\n" ::); }
__device__ __forceinline__ void cp_wait0()  { asm volatile("cp.async.wait_group 0;\n" ::); }

__device__ __forceinline__ void ldsm4(uint32_t* r, uint32_t addr) {
    asm volatile("ldmatrix.sync.aligned.m8n8.x4.shared.b16 {%0,%1,%2,%3}, [%4];\n"
                 : "=r"(r[0]), "=r"(r[1]), "=r"(r[2]), "=r"(r[3]) : "r"(addr));
}
__device__ __forceinline__ void mma16816(float* c, const uint32_t* a, const uint32_t* b) {
    asm volatile(
        "mma.sync.aligned.m16n8k16.row.col.f32.bf16.bf16.f32 "
        "{%0,%1,%2,%3}, {%4,%5,%6,%7}, {%8,%9}, {%0,%1,%2,%3};\n"
        : "+f"(c[0]), "+f"(c[1]), "+f"(c[2]), "+f"(c[3])
        : "r"(a[0]), "r"(a[1]), "r"(a[2]), "r"(a[3]), "r"(b[0]), "r"(b[1]));
}

__device__ __forceinline__ uint32_t rotl32(uint32_t v, int d) { return (v << d) | (v >> (32 - d)); }

// Exact JAX threefry2x32 block (key = [0, 42] for jax.random.key(42))
__device__ __forceinline__ uint2 threefry2x32(uint32_t k0, uint32_t k1, uint32_t x0, uint32_t x1) {
    uint32_t ks2 = k0 ^ k1 ^ 0x1BD11BDAu;
    x0 += k0; x1 += k1;
#define TF_R4(a,b,c,d) \
    { x0 += x1; x1 = rotl32(x1,a); x1 ^= x0; \
      x0 += x1; x1 = rotl32(x1,b); x1 ^= x0; \
      x0 += x1; x1 = rotl32(x1,c); x1 ^= x0; \
      x0 += x1; x1 = rotl32(x1,d); x1 ^= x0; }
    TF_R4(13,15,26,6);  x0 += k1;  x1 += ks2 + 1u;
    TF_R4(17,29,16,24); x0 += ks2; x1 += k0  + 2u;
    TF_R4(13,15,26,6);  x0 += k0;  x1 += k1  + 3u;
    TF_R4(17,29,16,24); x0 += k1;  x1 += ks2 + 4u;
    TF_R4(13,15,26,6);  x0 += ks2; x1 += k0  + 5u;
#undef TF_R4
    return make_uint2(x0, x1);
}

// JAX partitionable threefry random_bits (bit_width=32): xor-fold of both lanes.
__device__ __forceinline__ uint32_t jax_random_bits32(uint32_t i) {
    uint2 o = threefry2x32(0u, 42u, 0u, i);   // hi(i)=0 for i < 2^32
    return o.x ^ o.y;
}

// ---------------- kernel 1/2: row L2 normalize -> bf16 (dst chosen in DEVICE code) ----------------
__global__ void normalize_kernel(const float* __restrict__ src,
                                 int real_rows, int which) {
    __nv_bfloat16* dstb = which ? g_projn_bf16 : g_embn_bf16;   // device-side symbol ref
    int r = blockIdx.x;          // one row per CTA, 128 threads
    int tid = threadIdx.x;
    if (r >= real_rows) {        // zero-pad rows (embeddings padding)
        ushort4 z; z.x = z.y = z.z = z.w = 0;
        ((ushort4*)(dstb + (size_t)r * EDIM))[tid] = z;
        return;
    }
    float4 v = ((const float4*)(src + (size_t)r * EDIM))[tid];
    float ss = v.x * v.x + v.y * v.y + v.z * v.z + v.w * v.w;
    #pragma unroll
    for (int o = 16; o; o >>= 1) ss += __shfl_xor_sync(0xffffffffu, ss, o);
    __shared__ float wsum[4];
    if ((tid & 31) == 0) wsum[tid >> 5] = ss;
    __syncthreads();
    float tot = wsum[0] + wsum[1] + wsum[2] + wsum[3];
    float denom = fmaxf(sqrtf(tot), NORM_EPS);
    ushort4 b;
    b.x = __bfloat16_as_ushort(__float2bfloat16(v.x / denom));
    b.y = __bfloat16_as_ushort(__float2bfloat16(v.y / denom));
    b.z = __bfloat16_as_ushort(__float2bfloat16(v.z / denom));
    b.w = __bfloat16_as_ushort(__float2bfloat16(v.w / denom));
    ((ushort4*)(dstb + (size_t)r * EDIM))[tid] = b;
}

// ---------------- kernel 3: bf16 MMA GEMM (128x128 tile) + fused per-tile top-8 ----------------
// grid (NTILE, MROWS/BM), block 256 (8 warps: 4 over M x 2 over N, warp tile 32x64)
__global__ void __launch_bounds__(256) gemm_topk_kernel() {
    extern __shared__ char smem[];
    const int tid = threadIdx.x, lane = tid & 31, wid = tid >> 5;
    const int bn = blockIdx.x, bm = blockIdx.y;
    const int m0 = bm * BM, n0 = bn * BN;

    uint32_t sbase = (uint32_t)__cvta_generic_to_shared(smem);
    uint32_t aBase[2] = { sbase,                    sbase + BM * LDA * 2 };
    uint32_t bBase[2] = { sbase + 2 * BM * LDA * 2, sbase + 2 * BM * LDA * 2 + BN * LDB * 2 };

    float acc[2][8][4];
    #pragma unroll
    for (int mi = 0; mi < 2; mi++)
        #pragma unroll
        for (int ni = 0; ni < 8; ni++)
            #pragma unroll
            for (int q = 0; q < 4; q++) acc[mi][ni][q] = 0.f;

    const int wm0 = (wid >> 1) * 32;     // 4 warps over M
    const int wn  = wid & 1;             // 2 warps over N
    const int wn0 = wn * 64;

    auto loadA = [&](int kc, int buf) {
        const __nv_bfloat16* gp = g_projn_bf16 + (size_t)m0 * EDIM + kc * BK;
        #pragma unroll
        for (int i = 0; i < 2; i++) {
            int vId = tid + i * 256;
            int row = vId >> 2, q = vId & 3;
            cp16(aBase[buf] + (row * LDA + q * 8) * 2, gp + (size_t)row * EDIM + q * 8);
        }
    };
    auto loadB = [&](int kc, int buf) {
        const __nv_bfloat16* gb = g_embn_bf16 + (size_t)n0 * EDIM + kc * BK;
        #pragma unroll
        for (int i = 0; i < 2; i++) {
            int vId = tid + i * 256;
            int row = vId >> 2, q = vId & 3;
            cp16(bBase[buf] + (row * LDB + q * 8) * 2, gb + (size_t)row * EDIM + q * 8);
        }
    };

    loadA(0, 0); loadB(0, 0); cp_commit();

    const int aRow = lane & 15;                    // ldmatrix A addressing
    const int aK   = (lane >> 4) << 3;
    const int bN   = (lane & 7) + (((lane >> 4) & 1) << 3);
    const int bK   = ((lane >> 3) & 1) << 3;

    for (int kc = 0; kc < NKC; kc++) {
        cp_wait0();
        __syncthreads();
        if (kc + 1 < NKC) { loadA(kc + 1, (kc + 1) & 1); loadB(kc + 1, (kc + 1) & 1); cp_commit(); }
        int buf = kc & 1;
        #pragma unroll
        for (int s = 0; s < 2; s++) {
            uint32_t a[2][4], b[8][2];
            int k16 = s * 16;
            #pragma unroll
            for (int mi = 0; mi < 2; mi++) {
                uint32_t addr = aBase[buf] + (((wm0 + mi * 16 + aRow) * LDA) + k16 + aK) * 2;
                ldsm4(a[mi], addr);
            }
            #pragma unroll
            for (int p = 0; p < 4; p++) {
                uint32_t tmp[4];
                uint32_t addr = bBase[buf] + (((wn0 + p * 16 + bN) * LDB) + k16 + bK) * 2;
                ldsm4(tmp, addr);
                b[2 * p][0] = tmp[0]; b[2 * p][1] = tmp[1];
                b[2 * p + 1][0] = tmp[2]; b[2 * p + 1][1] = tmp[3];
            }
            #pragma unroll
            for (int mi = 0; mi < 2; mi++)
                #pragma unroll
                for (int ni = 0; ni < 8; ni++)
                    mma16816(acc[mi][ni], a[mi], b[ni]);
        }
    }

    // ---- fused epilogue: stage scores in two 64-col halves, per-row top-8 ----
    float* sc = (float*)smem;                    // [128][66] = 33792B, reuses pipeline smem
    const int g = lane >> 2, t4 = lane & 3;
    float tv[KEEP]; int ti[KEEP]; int cnt = 0;

    #pragma unroll
    for (int h = 0; h < 2; h++) {
        __syncthreads();                         // previous smem use finished
        if (wn == h) {
            #pragma unroll
            for (int mi = 0; mi < 2; mi++)
                #pragma unroll
                for (int ni = 0; ni < 8; ni++) {
                    int r = wm0 + mi * 16 + g;
                    int c = ni * 8 + t4 * 2;
                    sc[r * 66 + c]           = acc[mi][ni][0];
                    sc[r * 66 + c + 1]       = acc[mi][ni][1];
                    sc[(r + 8) * 66 + c]     = acc[mi][ni][2];
                    sc[(r + 8) * 66 + c + 1] = acc[mi][ni][3];
                }
        }
        __syncthreads();
        if (tid < 128) {
            int r = tid;
            #pragma unroll 4
            for (int c = 0; c < 64; c++) {
                int gcol = n0 + h * 64 + c;
                if (gcol >= V_REAL) break;
                float v = sc[r * 66 + c];
                if (cnt == KEEP && v <= tv[KEEP - 1]) continue;
                int p = (cnt < KEEP) ? cnt : (KEEP - 1);
                while (p > 0 && tv[p - 1] < v) { tv[p] = tv[p - 1]; ti[p] = ti[p - 1]; p--; }
                tv[p] = v; ti[p] = gcol;
                if (cnt < KEEP) cnt++;
            }
        }
    }
    if (tid < 128) {
        for (int j = cnt; j < KEEP; j++) { tv[j] = -FLT_MAX_; ti[j] = -1; }
        float2* dst = g_cand + ((size_t)(m0 + tid) * NTILE + bn) * KEEP;
        #pragma unroll
        for (int j = 0; j < KEEP; j++) dst[j] = make_float2(tv[j], __int_as_float(ti[j]));
    }
}

// ---------------- kernel 4: merge candidates, fp32 rescore, top-8, gumbel sample ----------------
__global__ void __launch_bounds__(256) merge_sample_kernel(const float* __restrict__ proj_raw,
                                                           const float* __restrict__ emb_raw,
                                                           float* __restrict__ out) {
    __shared__ float sh_proj[EDIM];
    __shared__ float sv[256 * TOPK];
    __shared__ int   si[256 * TOPK];
    __shared__ float red_v[8];
    __shared__ int   red_p[8];
    __shared__ int   sidx[NSEL];
    __shared__ float strue[NSEL];
    __shared__ float pnorm2[8];

    const int row = blockIdx.x;
    const int tid = threadIdx.x, lane = tid & 31, wid = tid >> 5;

    // normalize raw projection row into sh_proj
    {
        float ss = 0.f;
        for (int j = tid; j < EDIM; j += 256) {
            float x = proj_raw[(size_t)row * EDIM + j];
            sh_proj[j] = x;
            ss += x * x;
        }
        #pragma unroll
        for (int o = 16; o; o >>= 1) ss += __shfl_xor_sync(0xffffffffu, ss, o);
        if (lane == 0) pnorm2[wid] = ss;
        __syncthreads();
        float tot = 0.f;
        #pragma unroll
        for (int w = 0; w < 8; w++) tot += pnorm2[w];
        float denom = fmaxf(sqrtf(tot), NORM_EPS);
        __syncthreads();
        for (int j = tid; j < EDIM; j += 256) sh_proj[j] = sh_proj[j] / denom;
    }

    // thread-local top-8 scan over this row's 3144 candidates (coalesced stride-256)
    float tv[TOPK]; int ti[TOPK];
    #pragma unroll
    for (int k = 0; k < TOPK; k++) { tv[k] = -FLT_MAX_; ti[k] = -1; }
    const float2* crow = g_cand + (size_t)row * CAND;
    for (int j = tid; j < CAND; j += 256) {
        float2 cv = crow[j];
        float v = cv.x;
        if (v <= tv[TOPK - 1]) continue;
        int p = TOPK - 1;
        while (p > 0 && tv[p - 1] < v) { tv[p] = tv[p - 1]; ti[p] = ti[p - 1]; p--; }
        tv[p] = v; ti[p] = __float_as_int(cv.y);
    }
    #pragma unroll
    for (int k = 0; k < TOPK; k++) { sv[tid * TOPK + k] = tv[k]; si[tid * TOPK + k] = ti[k]; }
    __syncthreads();

    // block top-NSEL via iterative argmax over the 2048 staged candidates
    for (int it = 0; it < NSEL; it++) {
        float bv = -FLT_MAX_; int bp = 0;
        #pragma unroll
        for (int k = 0; k < TOPK; k++) {
            int j = tid + k * 256;
            float v = sv[j];
            if (v > bv) { bv = v; bp = j; }
        }
        #pragma unroll
        for (int o = 16; o; o >>= 1) {
            float ov = __shfl_down_sync(0xffffffffu, bv, o);
            int   op = __shfl_down_sync(0xffffffffu, bp, o);
            if (ov > bv) { bv = ov; bp = op; }
        }
        if (lane == 0) { red_v[wid] = bv; red_p[wid] = bp; }
        __syncthreads();
        if (tid == 0) {
            float m = red_v[0]; int p = red_p[0];
            #pragma unroll
            for (int w = 1; w < 8; w++) if (red_v[w] > m) { m = red_v[w]; p = red_p[w]; }
            sidx[it] = si[p];
            sv[p] = -FLT_MAX_;
        }
        __syncthreads();
    }

    // exact fp32 rescore: s = <proj_n, emb_raw[idx]> / max(||emb_raw[idx]||, eps)
    for (int c = wid; c < NSEL; c += 8) {
        int idx = sidx[c];
        float s = 0.f, e2 = 0.f;
        if (idx >= 0) {
            const float* e = emb_raw + (size_t)idx * EDIM;
            for (int j = lane; j < EDIM; j += 32) {
                float ev = e[j];
                s  = fmaf(sh_proj[j], ev, s);
                e2 = fmaf(ev, ev, e2);
            }
        }
        #pragma unroll
        for (int o = 16; o; o >>= 1) {
            s  += __shfl_xor_sync(0xffffffffu, s, o);
            e2 += __shfl_xor_sync(0xffffffffu, e2, o);
        }
        if (lane == 0) strue[c] = (idx >= 0) ? s / fmaxf(sqrtf(e2), NORM_EPS) : -FLT_MAX_;
    }
    __syncthreads();

    if (tid == 0) {
        // stable top-8: val desc, index asc (matches lax.top_k)
        float fv[TOPK]; int fi[TOPK];
        unsigned used = 0;
        for (int r = 0; r < TOPK; r++) {
            int best = -1; float bv = 0.f; int bi = 0;
            for (int c = 0; c < NSEL; c++) {
                if ((used >> c) & 1u) continue;
                float v = strue[c]; int ix = sidx[c];
                if (best < 0 || v > bv || (v == bv && ix < bi)) { best = c; bv = v; bi = ix; }
            }
            used |= 1u << best;
            fv[r] = bv; fi[r] = bi;
        }
        // gumbel-argmax sampling — partitionable threefry (xor-fold) scheme
        float m = -FLT_MAX_; int arg = 0;
        #pragma unroll
        for (int k = 0; k < TOPK; k++) {
            unsigned i = (unsigned)row * TOPK + k;
            unsigned bits = jax_random_bits32(i);
            float f = __uint_as_float((bits >> 9) | 0x3f800000u) - 1.0f;
            float u = fmaxf(TINY_F, f);
            float gmb = -logf(-logf(u));
            float t = fv[k] + gmb;     // TEMPERATURE = 1.0
            if (t > m) { m = t; arg = k; }
        }
        out[row] = (float)fi[arg];     // output compared as float32
    }
}

// ---------------- launcher ----------------
extern "C" void kernel_launch(void* const* d_in, const int* in_sizes, int n_in,
                              void* d_out, int out_size) {
    // Robust input resolution: largest input = embeddings, 2nd largest = projections.
    int ie = 0, ip = 0;
    long b1 = -1, b2 = -1;
    for (int i = 0; i < n_in; i++) {
        long s = in_sizes[i];
        if (s > b1)      { b2 = b1; ip = ie; b1 = s; ie = i; }
        else if (s > b2) { b2 = s; ip = i; }
    }
    const float* emb  = (const float*)d_in[ie];   // [50257,512]
    const float* proj = (const float*)d_in[ip];   // [4,1024,512]
    float* out = (float*)d_out;                   // [4,1024] float32 token ids

    normalize_kernel<<<VPAD, 128>>>(emb, V_REAL, /*which=*/0);
    normalize_kernel<<<MROWS, 128>>>(proj, MROWS, /*which=*/1);
    gemm_topk_kernel<<<dim3(NTILE, MROWS / BM), 256, SMEM_GEMM>>>();
    merge_sample_kernel<<<MROWS, 256>>>(proj, emb, out);
}

// round 10
// speedup vs baseline: 2.4154x; 2.4154x over previous
#include <cuda_runtime.h>
#include <cuda_bf16.h>
#include <cstdint>

// ---------------- problem constants ----------------
#define V_REAL 50257
#define BN     128
#define NTILE  393                 // ceil(50257/128)
#define VPAD   (NTILE*BN)          // 50304
#define EDIM   512
#define MROWS  4096                // 4*1024
#define TOPK   8
#define NSEL   16                  // candidates rescored exactly
#define KEEP   8                   // per-tile top-8 kept
#define CAND   (NTILE*KEEP)        // 3144 candidates per row

// GEMM tiling
#define BM 128
#define BK 32
#define NKC (EDIM/BK)              // 16
#define LDA 40                     // bf16 elems, padded (80B rows, 16B aligned)
#define LDB 40

#define FLT_MAX_ 3.402823466e+38f
#define TINY_F   1.17549435e-38f   // FLT_MIN (jnp.finfo(f32).tiny)
#define NORM_EPS 1e-12f

// Dynamic smem: pipeline 40960B; epilogue reuses it as sc[128][66] = 33792B
#define SMEM_GEMM 40960

// ---------------- scratch (device globals; no allocation) ----------------
static __device__ __nv_bfloat16 g_embn_bf16[(size_t)VPAD * EDIM];   // ~51.5 MB
static __device__ __nv_bfloat16 g_projn_bf16[(size_t)MROWS * EDIM]; // 4 MB
static __device__ float2        g_cand[(size_t)MROWS * CAND];       // ~103 MB

// ---------------- helpers ----------------
__device__ __forceinline__ void cp16(uint32_t dst, const void* src) {
    asm volatile("cp.async.cg.shared.global [%0], [%1], 16;\n" :: "r"(dst), "l"(src));
}
__device__ __forceinline__ void cp_commit() { asm volatile("cp.async.commit_group;\n" ::); }
__device__ __forceinline__ void cp_wait0()  { asm volatile("cp.async.wait_group 0;\n" ::); }

__device__ __forceinline__ void ldsm4(uint32_t* r, uint32_t addr) {
    asm volatile("ldmatrix.sync.aligned.m8n8.x4.shared.b16 {%0,%1,%2,%3}, [%4];\n"
                 : "=r"(r[0]), "=r"(r[1]), "=r"(r[2]), "=r"(r[3]) : "r"(addr));
}
__device__ __forceinline__ void mma16816(float* c, const uint32_t* a, const uint32_t* b) {
    asm volatile(
        "mma.sync.aligned.m16n8k16.row.col.f32.bf16.bf16.f32 "
        "{%0,%1,%2,%3}, {%4,%5,%6,%7}, {%8,%9}, {%0,%1,%2,%3};\n"
        : "+f"(c[0]), "+f"(c[1]), "+f"(c[2]), "+f"(c[3])
        : "r"(a[0]), "r"(a[1]), "r"(a[2]), "r"(a[3]), "r"(b[0]), "r"(b[1]));
}

__device__ __forceinline__ uint32_t rotl32(uint32_t v, int d) { return (v << d) | (v >> (32 - d)); }

// Exact JAX threefry2x32 block (key = [0, 42] for jax.random.key(42))
__device__ __forceinline__ uint2 threefry2x32(uint32_t k0, uint32_t k1, uint32_t x0, uint32_t x1) {
    uint32_t ks2 = k0 ^ k1 ^ 0x1BD11BDAu;
    x0 += k0; x1 += k1;
#define TF_R4(a,b,c,d) \
    { x0 += x1; x1 = rotl32(x1,a); x1 ^= x0; \
      x0 += x1; x1 = rotl32(x1,b); x1 ^= x0; \
      x0 += x1; x1 = rotl32(x1,c); x1 ^= x0; \
      x0 += x1; x1 = rotl32(x1,d); x1 ^= x0; }
    TF_R4(13,15,26,6);  x0 += k1;  x1 += ks2 + 1u;
    TF_R4(17,29,16,24); x0 += ks2; x1 += k0  + 2u;
    TF_R4(13,15,26,6);  x0 += k0;  x1 += k1  + 3u;
    TF_R4(17,29,16,24); x0 += k1;  x1 += ks2 + 4u;
    TF_R4(13,15,26,6);  x0 += ks2; x1 += k0  + 5u;
#undef TF_R4
    return make_uint2(x0, x1);
}

// JAX partitionable threefry random_bits (bit_width=32): xor-fold of both lanes.
__device__ __forceinline__ uint32_t jax_random_bits32(uint32_t i) {
    uint2 o = threefry2x32(0u, 42u, 0u, i);   // hi(i)=0 for i < 2^32
    return o.x ^ o.y;
}

// Branchless register-resident top-8 insert: tv sorted descending, constant
// indices only (NO local memory). Guard before calling: v > tv[7].
#define TOP8_INSERT(tv, ti, v, idx)                                   \
    {                                                                 \
        float _cv = (v); int _ci = (idx);                             \
        _Pragma("unroll")                                             \
        for (int _k = 0; _k < 8; _k++) {                              \
            bool _gt = _cv > tv[_k];                                  \
            float _ov = tv[_k]; int _oi = ti[_k];                     \
            tv[_k] = _gt ? _cv : tv[_k];                              \
            ti[_k] = _gt ? _ci : ti[_k];                              \
            _cv = _gt ? _ov : _cv;                                    \
            _ci = _gt ? _oi : _ci;                                    \
        }                                                             \
    }

// ---------------- kernel 1/2: row L2 normalize -> bf16 (dst chosen in DEVICE code) ----------------
__global__ void normalize_kernel(const float* __restrict__ src,
                                 int real_rows, int which) {
    __nv_bfloat16* dstb = which ? g_projn_bf16 : g_embn_bf16;   // device-side symbol ref
    int r = blockIdx.x;          // one row per CTA, 128 threads
    int tid = threadIdx.x;
    if (r >= real_rows) {        // zero-pad rows (embeddings padding)
        ushort4 z; z.x = z.y = z.z = z.w = 0;
        ((ushort4*)(dstb + (size_t)r * EDIM))[tid] = z;
        return;
    }
    float4 v = ((const float4*)(src + (size_t)r * EDIM))[tid];
    float ss = v.x * v.x + v.y * v.y + v.z * v.z + v.w * v.w;
    #pragma unroll
    for (int o = 16; o; o >>= 1) ss += __shfl_xor_sync(0xffffffffu, ss, o);
    __shared__ float wsum[4];
    if ((tid & 31) == 0) wsum[tid >> 5] = ss;
    __syncthreads();
    float tot = wsum[0] + wsum[1] + wsum[2] + wsum[3];
    float denom = fmaxf(sqrtf(tot), NORM_EPS);
    ushort4 b;
    b.x = __bfloat16_as_ushort(__float2bfloat16(v.x / denom));
    b.y = __bfloat16_as_ushort(__float2bfloat16(v.y / denom));
    b.z = __bfloat16_as_ushort(__float2bfloat16(v.z / denom));
    b.w = __bfloat16_as_ushort(__float2bfloat16(v.w / denom));
    ((ushort4*)(dstb + (size_t)r * EDIM))[tid] = b;
}

// ---------------- kernel 3: bf16 MMA GEMM (128x128 tile) + fused per-tile top-8 ----------------
// grid (NTILE, MROWS/BM), block 256 (8 warps: 4 over M x 2 over N, warp tile 32x64)
__global__ void __launch_bounds__(256) gemm_topk_kernel() {
    extern __shared__ char smem[];
    const int tid = threadIdx.x, lane = tid & 31, wid = tid >> 5;
    const int bn = blockIdx.x, bm = blockIdx.y;
    const int m0 = bm * BM, n0 = bn * BN;

    uint32_t sbase = (uint32_t)__cvta_generic_to_shared(smem);
    uint32_t aBase[2] = { sbase,                    sbase + BM * LDA * 2 };
    uint32_t bBase[2] = { sbase + 2 * BM * LDA * 2, sbase + 2 * BM * LDA * 2 + BN * LDB * 2 };

    float acc[2][8][4];
    #pragma unroll
    for (int mi = 0; mi < 2; mi++)
        #pragma unroll
        for (int ni = 0; ni < 8; ni++)
            #pragma unroll
            for (int q = 0; q < 4; q++) acc[mi][ni][q] = 0.f;

    const int wm0 = (wid >> 1) * 32;     // 4 warps over M
    const int wn  = wid & 1;             // 2 warps over N
    const int wn0 = wn * 64;

    auto loadA = [&](int kc, int buf) {
        const __nv_bfloat16* gp = g_projn_bf16 + (size_t)m0 * EDIM + kc * BK;
        #pragma unroll
        for (int i = 0; i < 2; i++) {
            int vId = tid + i * 256;
            int row = vId >> 2, q = vId & 3;
            cp16(aBase[buf] + (row * LDA + q * 8) * 2, gp + (size_t)row * EDIM + q * 8);
        }
    };
    auto loadB = [&](int kc, int buf) {
        const __nv_bfloat16* gb = g_embn_bf16 + (size_t)n0 * EDIM + kc * BK;
        #pragma unroll
        for (int i = 0; i < 2; i++) {
            int vId = tid + i * 256;
            int row = vId >> 2, q = vId & 3;
            cp16(bBase[buf] + (row * LDB + q * 8) * 2, gb + (size_t)row * EDIM + q * 8);
        }
    };

    loadA(0, 0); loadB(0, 0); cp_commit();

    const int aRow = lane & 15;                    // ldmatrix A addressing
    const int aK   = (lane >> 4) << 3;
    const int bN   = (lane & 7) + (((lane >> 4) & 1) << 3);
    const int bK   = ((lane >> 3) & 1) << 3;

    for (int kc = 0; kc < NKC; kc++) {
        cp_wait0();
        __syncthreads();
        if (kc + 1 < NKC) { loadA(kc + 1, (kc + 1) & 1); loadB(kc + 1, (kc + 1) & 1); cp_commit(); }
        int buf = kc & 1;
        #pragma unroll
        for (int s = 0; s < 2; s++) {
            uint32_t a[2][4], b[8][2];
            int k16 = s * 16;
            #pragma unroll
            for (int mi = 0; mi < 2; mi++) {
                uint32_t addr = aBase[buf] + (((wm0 + mi * 16 + aRow) * LDA) + k16 + aK) * 2;
                ldsm4(a[mi], addr);
            }
            #pragma unroll
            for (int p = 0; p < 4; p++) {
                uint32_t tmp[4];
                uint32_t addr = bBase[buf] + (((wn0 + p * 16 + bN) * LDB) + k16 + bK) * 2;
                ldsm4(tmp, addr);
                b[2 * p][0] = tmp[0]; b[2 * p][1] = tmp[1];
                b[2 * p + 1][0] = tmp[2]; b[2 * p + 1][1] = tmp[3];
            }
            #pragma unroll
            for (int mi = 0; mi < 2; mi++)
                #pragma unroll
                for (int ni = 0; ni < 8; ni++)
                    mma16816(acc[mi][ni], a[mi], b[ni]);
        }
    }

    // ---- fused epilogue: stage scores in two 64-col halves, per-row top-8 ----
    // Top-8 kept in REGISTERS with unrolled branchless inserts (no local mem).
    float* sc = (float*)smem;                    // [128][66] = 33792B, reuses pipeline smem
    const int g = lane >> 2, t4 = lane & 3;
    float tv[KEEP]; int ti[KEEP];
    #pragma unroll
    for (int k = 0; k < KEEP; k++) { tv[k] = -FLT_MAX_; ti[k] = -1; }

    const int colmax = V_REAL - n0;              // >= 81 for the last tile

    #pragma unroll
    for (int h = 0; h < 2; h++) {
        __syncthreads();                         // previous smem use finished
        if (wn == h) {
            #pragma unroll
            for (int mi = 0; mi < 2; mi++)
                #pragma unroll
                for (int ni = 0; ni < 8; ni++) {
                    int r = wm0 + mi * 16 + g;
                    int c = ni * 8 + t4 * 2;
                    sc[r * 66 + c]           = acc[mi][ni][0];
                    sc[r * 66 + c + 1]       = acc[mi][ni][1];
                    sc[(r + 8) * 66 + c]     = acc[mi][ni][2];
                    sc[(r + 8) * 66 + c + 1] = acc[mi][ni][3];
                }
        }
        __syncthreads();
        if (tid < 128) {
            const float* rowp = sc + tid * 66;
            #pragma unroll 8
            for (int c = 0; c < 64; c++) {
                int col = h * 64 + c;
                float v = rowp[c];
                if (v > tv[KEEP - 1] && col < colmax) {
                    TOP8_INSERT(tv, ti, v, n0 + col);
                }
            }
        }
    }
    if (tid < 128) {
        float2* dst = g_cand + ((size_t)(m0 + tid) * NTILE + bn) * KEEP;
        #pragma unroll
        for (int j = 0; j < KEEP; j++) dst[j] = make_float2(tv[j], __int_as_float(ti[j]));
    }
}

// ---------------- kernel 4: merge candidates, fp32 rescore, top-8, gumbel sample ----------------
__global__ void __launch_bounds__(256) merge_sample_kernel(const float* __restrict__ proj_raw,
                                                           const float* __restrict__ emb_raw,
                                                           float* __restrict__ out) {
    __shared__ float sh_proj[EDIM];
    __shared__ float sv[256 * TOPK];
    __shared__ int   si[256 * TOPK];
    __shared__ float red_v[8];
    __shared__ int   red_p[8];
    __shared__ int   sidx[NSEL];
    __shared__ float strue[NSEL];
    __shared__ float pnorm2[8];

    const int row = blockIdx.x;
    const int tid = threadIdx.x, lane = tid & 31, wid = tid >> 5;

    // normalize raw projection row into sh_proj
    {
        float ss = 0.f;
        for (int j = tid; j < EDIM; j += 256) {
            float x = proj_raw[(size_t)row * EDIM + j];
            sh_proj[j] = x;
            ss += x * x;
        }
        #pragma unroll
        for (int o = 16; o; o >>= 1) ss += __shfl_xor_sync(0xffffffffu, ss, o);
        if (lane == 0) pnorm2[wid] = ss;
        __syncthreads();
        float tot = 0.f;
        #pragma unroll
        for (int w = 0; w < 8; w++) tot += pnorm2[w];
        float denom = fmaxf(sqrtf(tot), NORM_EPS);
        __syncthreads();
        for (int j = tid; j < EDIM; j += 256) sh_proj[j] = sh_proj[j] / denom;
    }

    // thread-local top-8 scan over this row's 3144 candidates (register inserts)
    float tv[TOPK]; int ti[TOPK];
    #pragma unroll
    for (int k = 0; k < TOPK; k++) { tv[k] = -FLT_MAX_; ti[k] = -1; }
    const float2* crow = g_cand + (size_t)row * CAND;
    for (int j = tid; j < CAND; j += 256) {
        float2 cv = crow[j];
        if (cv.x > tv[TOPK - 1]) {
            TOP8_INSERT(tv, ti, cv.x, __float_as_int(cv.y));
        }
    }
    #pragma unroll
    for (int k = 0; k < TOPK; k++) { sv[tid * TOPK + k] = tv[k]; si[tid * TOPK + k] = ti[k]; }
    __syncthreads();

    // block top-NSEL via iterative argmax over the 2048 staged candidates
    for (int it = 0; it < NSEL; it++) {
        float bv = -FLT_MAX_; int bp = 0;
        #pragma unroll
        for (int k = 0; k < TOPK; k++) {
            int j = tid + k * 256;
            float v = sv[j];
            if (v > bv) { bv = v; bp = j; }
        }
        #pragma unroll
        for (int o = 16; o; o >>= 1) {
            float ov = __shfl_down_sync(0xffffffffu, bv, o);
            int   op = __shfl_down_sync(0xffffffffu, bp, o);
            if (ov > bv) { bv = ov; bp = op; }
        }
        if (lane == 0) { red_v[wid] = bv; red_p[wid] = bp; }
        __syncthreads();
        if (tid == 0) {
            float m = red_v[0]; int p = red_p[0];
            #pragma unroll
            for (int w = 1; w < 8; w++) if (red_v[w] > m) { m = red_v[w]; p = red_p[w]; }
            sidx[it] = si[p];
            sv[p] = -FLT_MAX_;
        }
        __syncthreads();
    }

    // exact fp32 rescore: s = <proj_n, emb_raw[idx]> / max(||emb_raw[idx]||, eps)
    for (int c = wid; c < NSEL; c += 8) {
        int idx = sidx[c];
        float s = 0.f, e2 = 0.f;
        if (idx >= 0) {
            const float* e = emb_raw + (size_t)idx * EDIM;
            for (int j = lane; j < EDIM; j += 32) {
                float ev = e[j];
                s  = fmaf(sh_proj[j], ev, s);
                e2 = fmaf(ev, ev, e2);
            }
        }
        #pragma unroll
        for (int o = 16; o; o >>= 1) {
            s  += __shfl_xor_sync(0xffffffffu, s, o);
            e2 += __shfl_xor_sync(0xffffffffu, e2, o);
        }
        if (lane == 0) strue[c] = (idx >= 0) ? s / fmaxf(sqrtf(e2), NORM_EPS) : -FLT_MAX_;
    }
    __syncthreads();

    if (tid == 0) {
        // stable top-8: val desc, index asc (matches lax.top_k)
        float fv[TOPK]; int fi[TOPK];
        unsigned used = 0;
        for (int r = 0; r < TOPK; r++) {
            int best = -1; float bv = 0.f; int bi = 0;
            for (int c = 0; c < NSEL; c++) {
                if ((used >> c) & 1u) continue;
                float v = strue[c]; int ix = sidx[c];
                if (best < 0 || v > bv || (v == bv && ix < bi)) { best = c; bv = v; bi = ix; }
            }
            used |= 1u << best;
            fv[r] = bv; fi[r] = bi;
        }
        // gumbel-argmax sampling — partitionable threefry (xor-fold) scheme
        float m = -FLT_MAX_; int arg = 0;
        #pragma unroll
        for (int k = 0; k < TOPK; k++) {
            unsigned i = (unsigned)row * TOPK + k;
            unsigned bits = jax_random_bits32(i);
            float f = __uint_as_float((bits >> 9) | 0x3f800000u) - 1.0f;
            float u = fmaxf(TINY_F, f);
            float gmb = -logf(-logf(u));
            float t = fv[k] + gmb;     // TEMPERATURE = 1.0
            if (t > m) { m = t; arg = k; }
        }
        out[row] = (float)fi[arg];     // output compared as float32
    }
}

// ---------------- launcher ----------------
extern "C" void kernel_launch(void* const* d_in, const int* in_sizes, int n_in,
                              void* d_out, int out_size) {
    // Robust input resolution: largest input = embeddings, 2nd largest = projections.
    int ie = 0, ip = 0;
    long b1 = -1, b2 = -1;
    for (int i = 0; i < n_in; i++) {
        long s = in_sizes[i];
        if (s > b1)      { b2 = b1; ip = ie; b1 = s; ie = i; }
        else if (s > b2) { b2 = s; ip = i; }
    }
    const float* emb  = (const float*)d_in[ie];   // [50257,512]
    const float* proj = (const float*)d_in[ip];   // [4,1024,512]
    float* out = (float*)d_out;                   // [4,1024] float32 token ids

    normalize_kernel<<<VPAD, 128>>>(emb, V_REAL, /*which=*/0);
    normalize_kernel<<<MROWS, 128>>>(proj, MROWS, /*which=*/1);
    gemm_topk_kernel<<<dim3(NTILE, MROWS / BM), 256, SMEM_GEMM>>>();
    merge_sample_kernel<<<MROWS, 256>>>(proj, emb, out);
}

// round 12
// speedup vs baseline: 2.7997x; 1.1591x over previous
#include <cuda_runtime.h>
#include <cuda_bf16.h>
#include <cstdint>

// ---------------- problem constants ----------------
#define V_REAL 50257
#define EDIM   512
#define MROWS  4096
#define TOPK   8
#define NSEL   16

// GEMM structure: persistent over N within a group
#define GN   8                      // N groups (grid.x)
#define TPG  50                     // tiles per group
#define BN   128                    // tile width
#define VPAD (GN*TPG*BN)            // 51200 padded vocab
#define BM   128
#define BK   32
#define NKC  (EDIM/BK)              // 16
#define LDA  40                     // bf16 elems, padded (80B rows)
#define LDB  40
#define CAND (GN*TOPK)              // 64 candidates per row

#define FLT_MAX_ 3.402823466e+38f
#define TINY_F   1.17549435e-38f
#define NORM_EPS 1e-12f

// smem: pipeline A0,A1,B0,B1 = 40960 B; score staging 128*66*4 = 33792 B
#define SC_OFF    40960
#define SMEM_GEMM (40960 + 33792)   // 74752

// ---------------- scratch (device globals; only referenced from device code) ----------------
static __device__ __nv_bfloat16 g_embn_bf16[(size_t)VPAD * EDIM];   // ~52 MB
static __device__ __nv_bfloat16 g_projn_bf16[(size_t)MROWS * EDIM]; // 4 MB
static __device__ float2        g_cand[(size_t)MROWS * CAND];       // 2 MB

// ---------------- helpers ----------------
__device__ __forceinline__ void cp16(uint32_t dst, const void* src) {
    asm volatile("cp.async.cg.shared.global [%0], [%1], 16;\n" :: "r"(dst), "l"(src));
}
__device__ __forceinline__ void cp_commit() { asm volatile("cp.async.commit_group;\n" ::); }
__device__ __forceinline__ void cp_wait0()  { asm volatile("cp.async.wait_group 0;\n" ::); }

__device__ __forceinline__ void ldsm4(uint32_t* r, uint32_t addr) {
    asm volatile("ldmatrix.sync.aligned.m8n8.x4.shared.b16 {%0,%1,%2,%3}, [%4];\n"
                 : "=r"(r[0]), "=r"(r[1]), "=r"(r[2]), "=r"(r[3]) : "r"(addr));
}
__device__ __forceinline__ void mma16816(float* c, const uint32_t* a, const uint32_t* b) {
    asm volatile(
        "mma.sync.aligned.m16n8k16.row.col.f32.bf16.bf16.f32 "
        "{%0,%1,%2,%3}, {%4,%5,%6,%7}, {%8,%9}, {%0,%1,%2,%3};\n"
        : "+f"(c[0]), "+f"(c[1]), "+f"(c[2]), "+f"(c[3])
        : "r"(a[0]), "r"(a[1]), "r"(a[2]), "r"(a[3]), "r"(b[0]), "r"(b[1]));
}

__device__ __forceinline__ uint32_t rotl32(uint32_t v, int d) { return (v << d) | (v >> (32 - d)); }

// Exact JAX threefry2x32 (key = [0, 42])
__device__ __forceinline__ uint2 threefry2x32(uint32_t k0, uint32_t k1, uint32_t x0, uint32_t x1) {
    uint32_t ks2 = k0 ^ k1 ^ 0x1BD11BDAu;
    x0 += k0; x1 += k1;
#define TF_R4(a,b,c,d) \
    { x0 += x1; x1 = rotl32(x1,a); x1 ^= x0; \
      x0 += x1; x1 = rotl32(x1,b); x1 ^= x0; \
      x0 += x1; x1 = rotl32(x1,c); x1 ^= x0; \
      x0 += x1; x1 = rotl32(x1,d); x1 ^= x0; }
    TF_R4(13,15,26,6);  x0 += k1;  x1 += ks2 + 1u;
    TF_R4(17,29,16,24); x0 += ks2; x1 += k0  + 2u;
    TF_R4(13,15,26,6);  x0 += k0;  x1 += k1  + 3u;
    TF_R4(17,29,16,24); x0 += k1;  x1 += ks2 + 4u;
    TF_R4(13,15,26,6);  x0 += ks2; x1 += k0  + 5u;
#undef TF_R4
    return make_uint2(x0, x1);
}
// JAX partitionable random_bits (32-bit): xor-fold of both output lanes.
__device__ __forceinline__ uint32_t jax_random_bits32(uint32_t i) {
    uint2 o = threefry2x32(0u, 42u, 0u, i);
    return o.x ^ o.y;
}

// Branchless register top-8 insert (constant indices only; no local memory).
#define TOP8_INSERT(tv, ti, v, idx)                                   \
    {                                                                 \
        float _cv = (v); int _ci = (idx);                             \
        _Pragma("unroll")                                             \
        for (int _k = 0; _k < 8; _k++) {                              \
            bool _gt = _cv > tv[_k];                                  \
            float _ov = tv[_k]; int _oi = ti[_k];                     \
            tv[_k] = _gt ? _cv : tv[_k];                              \
            ti[_k] = _gt ? _ci : ti[_k];                              \
            _cv = _gt ? _ov : _cv;                                    \
            _ci = _gt ? _oi : _ci;                                    \
        }                                                             \
    }

// ---------------- kernel 1/2: row L2 normalize -> bf16 ----------------
__global__ void normalize_kernel(const float* __restrict__ src, int real_rows, int which) {
    __nv_bfloat16* dstb = which ? g_projn_bf16 : g_embn_bf16;   // device-side symbol ref
    int r = blockIdx.x, tid = threadIdx.x;
    if (r >= real_rows) {
        ushort4 z; z.x = z.y = z.z = z.w = 0;
        ((ushort4*)(dstb + (size_t)r * EDIM))[tid] = z;
        return;
    }
    float4 v = ((const float4*)(src + (size_t)r * EDIM))[tid];
    float ss = v.x * v.x + v.y * v.y + v.z * v.z + v.w * v.w;
    #pragma unroll
    for (int o = 16; o; o >>= 1) ss += __shfl_xor_sync(0xffffffffu, ss, o);
    __shared__ float wsum[4];
    if ((tid & 31) == 0) wsum[tid >> 5] = ss;
    __syncthreads();
    float tot = wsum[0] + wsum[1] + wsum[2] + wsum[3];
    float denom = fmaxf(sqrtf(tot), NORM_EPS);
    ushort4 b;
    b.x = __bfloat16_as_ushort(__float2bfloat16(v.x / denom));
    b.y = __bfloat16_as_ushort(__float2bfloat16(v.y / denom));
    b.z = __bfloat16_as_ushort(__float2bfloat16(v.z / denom));
    b.w = __bfloat16_as_ushort(__float2bfloat16(v.w / denom));
    ((ushort4*)(dstb + (size_t)r * EDIM))[tid] = b;
}

// ---------------- kernel 3: persistent bf16 MMA GEMM + carried top-8 ----------------
// grid (GN, 32), block 256 (8 warps: 4 over M x 2 over N, warp tile 32x64).
// Each CTA: 128 M-rows, loops over TPG=50 N-tiles of 128 cols, carrying top-8.
__global__ void __launch_bounds__(256, 2) gemm_topk_kernel() {
    extern __shared__ char smem[];
    const int tid = threadIdx.x, lane = tid & 31, wid = tid >> 5;
    const int grp = blockIdx.x, bm = blockIdx.y;
    const int m0 = bm * BM;
    const int ncol0 = grp * TPG * BN;

    uint32_t sbase = (uint32_t)__cvta_generic_to_shared(smem);
    uint32_t aBase[2] = { sbase,                    sbase + BM * LDA * 2 };
    uint32_t bBase[2] = { sbase + 2 * BM * LDA * 2, sbase + 2 * BM * LDA * 2 + BN * LDB * 2 };
    float* sc = (float*)(smem + SC_OFF);          // [128][66] score staging

    const int wm0 = (wid >> 1) * 32;     // 4 warps over M
    const int wn  = wid & 1;             // 2 warps over N
    const int wn0 = wn * 64;

    auto loadA = [&](int kc, int buf) {
        const __nv_bfloat16* gp = g_projn_bf16 + (size_t)m0 * EDIM + kc * BK;
        #pragma unroll
        for (int i = 0; i < 2; i++) {
            int vId = tid + i * 256;
            int row = vId >> 2, q = vId & 3;
            cp16(aBase[buf] + (row * LDA + q * 8) * 2, gp + (size_t)row * EDIM + q * 8);
        }
    };
    auto loadB = [&](int t, int kc, int buf) {
        const __nv_bfloat16* gb = g_embn_bf16 + (size_t)(ncol0 + t * BN) * EDIM + kc * BK;
        #pragma unroll
        for (int i = 0; i < 2; i++) {
            int vId = tid + i * 256;
            int row = vId >> 2, q = vId & 3;
            cp16(bBase[buf] + (row * LDB + q * 8) * 2, gb + (size_t)row * EDIM + q * 8);
        }
    };

    const int aRow = lane & 15;                    // ldmatrix addressing
    const int aK   = (lane >> 4) << 3;
    const int bN   = (lane & 7) + (((lane >> 4) & 1) << 3);
    const int bK   = ((lane >> 3) & 1) << 3;
    const int g    = lane >> 2, t4 = lane & 3;

    // carried top-8 (registers, persist across all 50 tiles)
    float tv[TOPK]; int ti[TOPK];
    #pragma unroll
    for (int k = 0; k < TOPK; k++) { tv[k] = -FLT_MAX_; ti[k] = -1; }

    loadA(0, 0); loadB(0, 0, 0); cp_commit();

    for (int t = 0; t < TPG; t++) {
        float acc[2][8][4];
        #pragma unroll
        for (int mi = 0; mi < 2; mi++)
            #pragma unroll
            for (int ni = 0; ni < 8; ni++)
                #pragma unroll
                for (int q = 0; q < 4; q++) acc[mi][ni][q] = 0.f;

        for (int kc = 0; kc < NKC; kc++) {
            cp_wait0();
            __syncthreads();
            int nbuf = (kc + 1) & 1;
            if (kc + 1 < NKC) {
                loadA(kc + 1, nbuf); loadB(t, kc + 1, nbuf); cp_commit();
            } else if (t + 1 < TPG) {
                loadA(0, nbuf); loadB(t + 1, 0, nbuf); cp_commit();
            }
            int buf = kc & 1;
            #pragma unroll
            for (int s = 0; s < 2; s++) {
                uint32_t a[2][4], b[8][2];
                int k16 = s * 16;
                #pragma unroll
                for (int mi = 0; mi < 2; mi++) {
                    uint32_t addr = aBase[buf] + (((wm0 + mi * 16 + aRow) * LDA) + k16 + aK) * 2;
                    ldsm4(a[mi], addr);
                }
                #pragma unroll
                for (int p = 0; p < 4; p++) {
                    uint32_t tmp[4];
                    uint32_t addr = bBase[buf] + (((wn0 + p * 16 + bN) * LDB) + k16 + bK) * 2;
                    ldsm4(tmp, addr);
                    b[2 * p][0] = tmp[0]; b[2 * p][1] = tmp[1];
                    b[2 * p + 1][0] = tmp[2]; b[2 * p + 1][1] = tmp[3];
                }
                #pragma unroll
                for (int mi = 0; mi < 2; mi++)
                    #pragma unroll
                    for (int ni = 0; ni < 8; ni++)
                        mma16816(acc[mi][ni], a[mi], b[ni]);
            }
        }

        // ---- epilogue for tile t: stage to sc (separate smem), carried top-8 scan ----
        // (next tile's kc=0 cp.async prefetch proceeds in the background)
        const int tile_col0 = ncol0 + t * BN;
        #pragma unroll
        for (int h = 0; h < 2; h++) {
            __syncthreads();
            if (wn == h) {
                #pragma unroll
                for (int mi = 0; mi < 2; mi++)
                    #pragma unroll
                    for (int ni = 0; ni < 8; ni++) {
                        int r = wm0 + mi * 16 + g;
                        int c = ni * 8 + t4 * 2;
                        sc[r * 66 + c]           = acc[mi][ni][0];
                        sc[r * 66 + c + 1]       = acc[mi][ni][1];
                        sc[(r + 8) * 66 + c]     = acc[mi][ni][2];
                        sc[(r + 8) * 66 + c + 1] = acc[mi][ni][3];
                    }
            }
            __syncthreads();
            if (tid < 128) {
                const float* rowp = sc + tid * 66;
                int col0 = tile_col0 + h * 64;
                #pragma unroll 8
                for (int c = 0; c < 64; c++) {
                    float v = rowp[c];
                    int col = col0 + c;
                    if (v > tv[TOPK - 1] && col < V_REAL) {
                        TOP8_INSERT(tv, ti, v, col);
                    }
                }
            }
        }
    }

    // write carried top-8 for this (row, group)
    if (tid < 128) {
        float2* dst = g_cand + ((size_t)(m0 + tid) * GN + grp) * TOPK;
        #pragma unroll
        for (int j = 0; j < TOPK; j++) dst[j] = make_float2(tv[j], __int_as_float(ti[j]));
    }
}

// ---------------- kernel 4: merge 64 candidates, fp32 rescore, top-8, sample ----------------
__global__ void __launch_bounds__(256) merge_sample_kernel(const float* __restrict__ proj_raw,
                                                           const float* __restrict__ emb_raw,
                                                           float* __restrict__ out) {
    __shared__ float sh_proj[EDIM];
    __shared__ float sv[CAND];
    __shared__ int   si[CAND];
    __shared__ float red_v[8];
    __shared__ int   red_p[8];
    __shared__ int   sidx[NSEL];
    __shared__ float strue[NSEL];
    __shared__ float pnorm2[8];

    const int row = blockIdx.x;
    const int tid = threadIdx.x, lane = tid & 31, wid = tid >> 5;

    // normalize raw projection row
    {
        float ss = 0.f;
        for (int j = tid; j < EDIM; j += 256) {
            float x = proj_raw[(size_t)row * EDIM + j];
            sh_proj[j] = x;
            ss += x * x;
        }
        #pragma unroll
        for (int o = 16; o; o >>= 1) ss += __shfl_xor_sync(0xffffffffu, ss, o);
        if (lane == 0) pnorm2[wid] = ss;
        __syncthreads();
        float tot = 0.f;
        #pragma unroll
        for (int w = 0; w < 8; w++) tot += pnorm2[w];
        float denom = fmaxf(sqrtf(tot), NORM_EPS);
        __syncthreads();
        for (int j = tid; j < EDIM; j += 256) sh_proj[j] = sh_proj[j] / denom;
    }
    if (tid < CAND) {
        float2 cv = g_cand[(size_t)row * CAND + tid];
        sv[tid] = cv.x; si[tid] = __float_as_int(cv.y);
    }
    __syncthreads();

    // block top-NSEL by iterative argmax over the 64 candidates
    for (int it = 0; it < NSEL; it++) {
        float bv = -FLT_MAX_; int bp = 0;
        if (tid < CAND) { bv = sv[tid]; bp = tid; }
        #pragma unroll
        for (int o = 16; o; o >>= 1) {
            float ov = __shfl_down_sync(0xffffffffu, bv, o);
            int   op = __shfl_down_sync(0xffffffffu, bp, o);
            if (ov > bv) { bv = ov; bp = op; }
        }
        if (lane == 0) { red_v[wid] = bv; red_p[wid] = bp; }
        __syncthreads();
        if (tid == 0) {
            float m = red_v[0]; int p = red_p[0];
            #pragma unroll
            for (int w = 1; w < 8; w++) if (red_v[w] > m) { m = red_v[w]; p = red_p[w]; }
            sidx[it] = si[p];
            sv[p] = -FLT_MAX_;
        }
        __syncthreads();
    }

    // exact fp32 rescore: s = <proj_n, emb_raw[idx]> / max(||emb_raw[idx]||, eps)
    for (int c = wid; c < NSEL; c += 8) {
        int idx = sidx[c];
        float s = 0.f, e2 = 0.f;
        if (idx >= 0) {
            const float* e = emb_raw + (size_t)idx * EDIM;
            for (int j = lane; j < EDIM; j += 32) {
                float ev = e[j];
                s  = fmaf(sh_proj[j], ev, s);
                e2 = fmaf(ev, ev, e2);
            }
        }
        #pragma unroll
        for (int o = 16; o; o >>= 1) {
            s  += __shfl_xor_sync(0xffffffffu, s, o);
            e2 += __shfl_xor_sync(0xffffffffu, e2, o);
        }
        if (lane == 0) strue[c] = (idx >= 0) ? s / fmaxf(sqrtf(e2), NORM_EPS) : -FLT_MAX_;
    }
    __syncthreads();

    if (tid == 0) {
        // stable top-8: val desc, index asc (matches lax.top_k)
        float fv[TOPK]; int fi[TOPK];
        unsigned used = 0;
        for (int r = 0; r < TOPK; r++) {
            int best = -1; float bv = 0.f; int bi = 0;
            for (int c = 0; c < NSEL; c++) {
                if ((used >> c) & 1u) continue;
                float v = strue[c]; int ix = sidx[c];
                if (best < 0 || v > bv || (v == bv && ix < bi)) { best = c; bv = v; bi = ix; }
            }
            used |= 1u << best;
            fv[r] = bv; fi[r] = bi;
        }
        // gumbel-argmax sampling (partitionable threefry, xor-fold)
        float m = -FLT_MAX_; int arg = 0;
        #pragma unroll
        for (int k = 0; k < TOPK; k++) {
            unsigned i = (unsigned)row * TOPK + k;
            unsigned bits = jax_random_bits32(i);
            float f = __uint_as_float((bits >> 9) | 0x3f800000u) - 1.0f;
            float u = fmaxf(TINY_F, f);
            float gmb = -logf(-logf(u));
            float t = fv[k] + gmb;
            if (t > m) { m = t; arg = k; }
        }
        out[row] = (float)fi[arg];
    }
}

// ---------------- launcher ----------------
extern "C" void kernel_launch(void* const* d_in, const int* in_sizes, int n_in,
                              void* d_out, int out_size) {
    int ie = 0, ip = 0;
    long b1 = -1, b2 = -1;
    for (int i = 0; i < n_in; i++) {
        long s = in_sizes[i];
        if (s > b1)      { b2 = b1; ip = ie; b1 = s; ie = i; }
        else if (s > b2) { b2 = s; ip = i; }
    }
    const float* emb  = (const float*)d_in[ie];   // [50257,512]
    const float* proj = (const float*)d_in[ip];   // [4,1024,512]
    float* out = (float*)d_out;                   // [4,1024] float32 token ids

    cudaFuncSetAttribute(gemm_topk_kernel,
                         cudaFuncAttributeMaxDynamicSharedMemorySize, SMEM_GEMM);

    normalize_kernel<<<VPAD, 128>>>(emb, V_REAL, /*which=*/0);
    normalize_kernel<<<MROWS, 128>>>(proj, MROWS, /*which=*/1);
    gemm_topk_kernel<<<dim3(GN, 32), 256, SMEM_GEMM>>>();
    merge_sample_kernel<<<MROWS, 256>>>(proj, emb, out);
}

// round 13
// speedup vs baseline: 3.1768x; 1.1347x over previous
#include <cuda_runtime.h>
#include <cuda_bf16.h>
#include <cstdint>

// ---------------- problem constants ----------------
#define V_REAL 50257
#define EDIM   512
#define MROWS  4096
#define TOPK   8
#define NSEL   16

// GEMM structure: persistent over N within a group
#define GN   9                      // N groups (grid.x) -> 288 CTAs (2-wave balanced)
#define TPG  44                     // tiles per group
#define BN   128                    // tile width
#define VPAD (GN*TPG*BN)            // 50688 padded vocab
#define BM   128
#define BK   32
#define NKC  (EDIM/BK)              // 16
#define LDA  40                     // bf16 elems, padded (80B rows)
#define LDB  40
#define CAND (GN*TOPK)              // 72 candidates per row

#define FLT_MAX_ 3.402823466e+38f
#define TINY_F   1.17549435e-38f
#define NORM_EPS 1e-12f

// smem: 3 pipeline stages x (A 10240 + B 10240) = 61440; score staging 33792
#define STAGE_BYTES 20480
#define SC_OFF      61440
#define SMEM_GEMM   (61440 + 33792)   // 95232 -> 2 CTAs/SM

// ---------------- scratch (device globals; only referenced from device code) ----------------
static __device__ __nv_bfloat16 g_embn_bf16[(size_t)VPAD * EDIM];   // ~52 MB
static __device__ __nv_bfloat16 g_projn_bf16[(size_t)MROWS * EDIM]; // 4 MB
static __device__ float2        g_cand[(size_t)MROWS * CAND];       // ~2.4 MB

// ---------------- helpers ----------------
__device__ __forceinline__ void cp16(uint32_t dst, const void* src) {
    asm volatile("cp.async.cg.shared.global [%0], [%1], 16;\n" :: "r"(dst), "l"(src));
}
__device__ __forceinline__ void cp_commit() { asm volatile("cp.async.commit_group;\n" ::); }
__device__ __forceinline__ void cp_wait0()  { asm volatile("cp.async.wait_group 0;\n" ::); }
__device__ __forceinline__ void cp_wait1()  { asm volatile("cp.async.wait_group 1;\n" ::); }

__device__ __forceinline__ void ldsm4(uint32_t* r, uint32_t addr) {
    asm volatile("ldmatrix.sync.aligned.m8n8.x4.shared.b16 {%0,%1,%2,%3}, [%4];\n"
                 : "=r"(r[0]), "=r"(r[1]), "=r"(r[2]), "=r"(r[3]) : "r"(addr));
}
__device__ __forceinline__ void mma16816(float* c, const uint32_t* a, const uint32_t* b) {
    asm volatile(
        "mma.sync.aligned.m16n8k16.row.col.f32.bf16.bf16.f32 "
        "{%0,%1,%2,%3}, {%4,%5,%6,%7}, {%8,%9}, {%0,%1,%2,%3};\n"
        : "+f"(c[0]), "+f"(c[1]), "+f"(c[2]), "+f"(c[3])
        : "r"(a[0]), "r"(a[1]), "r"(a[2]), "r"(a[3]), "r"(b[0]), "r"(b[1]));
}

__device__ __forceinline__ uint32_t rotl32(uint32_t v, int d) { return (v << d) | (v >> (32 - d)); }

// Exact JAX threefry2x32 (key = [0, 42])
__device__ __forceinline__ uint2 threefry2x32(uint32_t k0, uint32_t k1, uint32_t x0, uint32_t x1) {
    uint32_t ks2 = k0 ^ k1 ^ 0x1BD11BDAu;
    x0 += k0; x1 += k1;
#define TF_R4(a,b,c,d) \
    { x0 += x1; x1 = rotl32(x1,a); x1 ^= x0; \
      x0 += x1; x1 = rotl32(x1,b); x1 ^= x0; \
      x0 += x1; x1 = rotl32(x1,c); x1 ^= x0; \
      x0 += x1; x1 = rotl32(x1,d); x1 ^= x0; }
    TF_R4(13,15,26,6);  x0 += k1;  x1 += ks2 + 1u;
    TF_R4(17,29,16,24); x0 += ks2; x1 += k0  + 2u;
    TF_R4(13,15,26,6);  x0 += k0;  x1 += k1  + 3u;
    TF_R4(17,29,16,24); x0 += k1;  x1 += ks2 + 4u;
    TF_R4(13,15,26,6);  x0 += ks2; x1 += k0  + 5u;
#undef TF_R4
    return make_uint2(x0, x1);
}
// JAX partitionable random_bits (32-bit): xor-fold of both output lanes.
__device__ __forceinline__ uint32_t jax_random_bits32(uint32_t i) {
    uint2 o = threefry2x32(0u, 42u, 0u, i);
    return o.x ^ o.y;
}

// Branchless register top-8 insert (constant indices only; no local memory).
#define TOP8_INSERT(tv, ti, v, idx)                                   \
    {                                                                 \
        float _cv = (v); int _ci = (idx);                             \
        _Pragma("unroll")                                             \
        for (int _k = 0; _k < 8; _k++) {                              \
            bool _gt = _cv > tv[_k];                                  \
            float _ov = tv[_k]; int _oi = ti[_k];                     \
            tv[_k] = _gt ? _cv : tv[_k];                              \
            ti[_k] = _gt ? _ci : ti[_k];                              \
            _cv = _gt ? _ov : _cv;                                    \
            _ci = _gt ? _oi : _ci;                                    \
        }                                                             \
    }

// ---------------- kernel 1/2: row L2 normalize -> bf16 ----------------
__global__ void normalize_kernel(const float* __restrict__ src, int real_rows, int which) {
    __nv_bfloat16* dstb = which ? g_projn_bf16 : g_embn_bf16;   // device-side symbol ref
    int r = blockIdx.x, tid = threadIdx.x;
    if (r >= real_rows) {
        ushort4 z; z.x = z.y = z.z = z.w = 0;
        ((ushort4*)(dstb + (size_t)r * EDIM))[tid] = z;
        return;
    }
    float4 v = ((const float4*)(src + (size_t)r * EDIM))[tid];
    float ss = v.x * v.x + v.y * v.y + v.z * v.z + v.w * v.w;
    #pragma unroll
    for (int o = 16; o; o >>= 1) ss += __shfl_xor_sync(0xffffffffu, ss, o);
    __shared__ float wsum[4];
    if ((tid & 31) == 0) wsum[tid >> 5] = ss;
    __syncthreads();
    float tot = wsum[0] + wsum[1] + wsum[2] + wsum[3];
    float denom = fmaxf(sqrtf(tot), NORM_EPS);
    ushort4 b;
    b.x = __bfloat16_as_ushort(__float2bfloat16(v.x / denom));
    b.y = __bfloat16_as_ushort(__float2bfloat16(v.y / denom));
    b.z = __bfloat16_as_ushort(__float2bfloat16(v.z / denom));
    b.w = __bfloat16_as_ushort(__float2bfloat16(v.w / denom));
    ((ushort4*)(dstb + (size_t)r * EDIM))[tid] = b;
}

// ---------------- kernel 3: persistent bf16 MMA GEMM + carried top-8 ----------------
// grid (GN, 32), block 256 (8 warps: 4 over M x 2 over N, warp tile 32x64).
// 3-stage cp.async pipeline (wait_group 1), carried top-8 across TPG tiles.
__global__ void __launch_bounds__(256, 2) gemm_topk_kernel() {
    extern __shared__ char smem[];
    const int tid = threadIdx.x, lane = tid & 31, wid = tid >> 5;
    const int grp = blockIdx.x, bm = blockIdx.y;
    const int m0 = bm * BM;
    const int ncol0 = grp * TPG * BN;

    uint32_t sbase = (uint32_t)__cvta_generic_to_shared(smem);
    float* sc = (float*)(smem + SC_OFF);          // [128][66] score staging

    const int wm0 = (wid >> 1) * 32;     // 4 warps over M
    const int wn  = wid & 1;             // 2 warps over N
    const int wn0 = wn * 64;

    // load A+B chunk c into stage st
    auto loadChunk = [&](int c, int st) {
        int t = c >> 4, kc = c & 15;
        uint32_t aB = sbase + st * STAGE_BYTES;
        uint32_t bB = aB + 10240;
        const __nv_bfloat16* gp = g_projn_bf16 + (size_t)m0 * EDIM + kc * BK;
        const __nv_bfloat16* gb = g_embn_bf16 + (size_t)(ncol0 + t * BN) * EDIM + kc * BK;
        #pragma unroll
        for (int i = 0; i < 2; i++) {
            int vId = tid + i * 256;
            int row = vId >> 2, q = vId & 3;
            cp16(aB + (row * LDA + q * 8) * 2, gp + (size_t)row * EDIM + q * 8);
            cp16(bB + (row * LDB + q * 8) * 2, gb + (size_t)row * EDIM + q * 8);
        }
    };

    const int aRow = lane & 15;                    // ldmatrix addressing
    const int aK   = (lane >> 4) << 3;
    const int bN   = (lane & 7) + (((lane >> 4) & 1) << 3);
    const int bK   = ((lane >> 3) & 1) << 3;
    const int g    = lane >> 2, t4 = lane & 3;

    // carried top-8 (registers, persist across all TPG tiles)
    float tv[TOPK]; int ti[TOPK];
    #pragma unroll
    for (int k = 0; k < TOPK; k++) { tv[k] = -FLT_MAX_; ti[k] = -1; }

    const int TOT = TPG * NKC;
    loadChunk(0, 0); cp_commit();
    loadChunk(1, 1); cp_commit();

    for (int t = 0; t < TPG; t++) {
        float acc[2][8][4];
        #pragma unroll
        for (int mi = 0; mi < 2; mi++)
            #pragma unroll
            for (int ni = 0; ni < 8; ni++)
                #pragma unroll
                for (int q = 0; q < 4; q++) acc[mi][ni][q] = 0.f;

        for (int kc = 0; kc < NKC; kc++) {
            const int c = t * NKC + kc;
            if (c + 1 < TOT) cp_wait1(); else cp_wait0();
            __syncthreads();
            if (c + 2 < TOT) { loadChunk(c + 2, (c + 2) % 3); cp_commit(); }

            uint32_t aBase = sbase + (c % 3) * STAGE_BYTES;
            uint32_t bBase = aBase + 10240;
            #pragma unroll
            for (int s = 0; s < 2; s++) {
                uint32_t a[2][4], b[8][2];
                int k16 = s * 16;
                #pragma unroll
                for (int mi = 0; mi < 2; mi++) {
                    uint32_t addr = aBase + (((wm0 + mi * 16 + aRow) * LDA) + k16 + aK) * 2;
                    ldsm4(a[mi], addr);
                }
                #pragma unroll
                for (int p = 0; p < 4; p++) {
                    uint32_t tmp[4];
                    uint32_t addr = bBase + (((wn0 + p * 16 + bN) * LDB) + k16 + bK) * 2;
                    ldsm4(tmp, addr);
                    b[2 * p][0] = tmp[0]; b[2 * p][1] = tmp[1];
                    b[2 * p + 1][0] = tmp[2]; b[2 * p + 1][1] = tmp[3];
                }
                #pragma unroll
                for (int mi = 0; mi < 2; mi++)
                    #pragma unroll
                    for (int ni = 0; ni < 8; ni++)
                        mma16816(acc[mi][ni], a[mi], b[ni]);
            }
        }

        // ---- epilogue for tile t: stage to sc (separate smem), carried top-8 scan ----
        const int tile_col0 = ncol0 + t * BN;
        #pragma unroll
        for (int h = 0; h < 2; h++) {
            __syncthreads();
            if (wn == h) {
                #pragma unroll
                for (int mi = 0; mi < 2; mi++)
                    #pragma unroll
                    for (int ni = 0; ni < 8; ni++) {
                        int r = wm0 + mi * 16 + g;
                        int c = ni * 8 + t4 * 2;
                        sc[r * 66 + c]           = acc[mi][ni][0];
                        sc[r * 66 + c + 1]       = acc[mi][ni][1];
                        sc[(r + 8) * 66 + c]     = acc[mi][ni][2];
                        sc[(r + 8) * 66 + c + 1] = acc[mi][ni][3];
                    }
            }
            __syncthreads();
            if (tid < 128) {
                const float* rowp = sc + tid * 66;
                int col0 = tile_col0 + h * 64;
                #pragma unroll 8
                for (int c = 0; c < 64; c++) {
                    float v = rowp[c];
                    int col = col0 + c;
                    if (v > tv[TOPK - 1] && col < V_REAL) {
                        TOP8_INSERT(tv, ti, v, col);
                    }
                }
            }
        }
    }

    // write carried top-8 for this (row, group)
    if (tid < 128) {
        float2* dst = g_cand + ((size_t)(m0 + tid) * GN + grp) * TOPK;
        #pragma unroll
        for (int j = 0; j < TOPK; j++) dst[j] = make_float2(tv[j], __int_as_float(ti[j]));
    }
}

// ---------------- kernel 4: merge 72 candidates, fp32 rescore, top-8, sample ----------------
__global__ void __launch_bounds__(256) merge_sample_kernel(const float* __restrict__ proj_raw,
                                                           const float* __restrict__ emb_raw,
                                                           float* __restrict__ out) {
    __shared__ float sh_proj[EDIM];
    __shared__ float sv[CAND];
    __shared__ int   si[CAND];
    __shared__ float red_v[8];
    __shared__ int   red_p[8];
    __shared__ int   sidx[NSEL];
    __shared__ float strue[NSEL];
    __shared__ float pnorm2[8];

    const int row = blockIdx.x;
    const int tid = threadIdx.x, lane = tid & 31, wid = tid >> 5;

    // normalize raw projection row
    {
        float ss = 0.f;
        for (int j = tid; j < EDIM; j += 256) {
            float x = proj_raw[(size_t)row * EDIM + j];
            sh_proj[j] = x;
            ss += x * x;
        }
        #pragma unroll
        for (int o = 16; o; o >>= 1) ss += __shfl_xor_sync(0xffffffffu, ss, o);
        if (lane == 0) pnorm2[wid] = ss;
        __syncthreads();
        float tot = 0.f;
        #pragma unroll
        for (int w = 0; w < 8; w++) tot += pnorm2[w];
        float denom = fmaxf(sqrtf(tot), NORM_EPS);
        __syncthreads();
        for (int j = tid; j < EDIM; j += 256) sh_proj[j] = sh_proj[j] / denom;
    }
    if (tid < CAND) {
        float2 cv = g_cand[(size_t)row * CAND + tid];
        sv[tid] = cv.x; si[tid] = __float_as_int(cv.y);
    }
    __syncthreads();

    // block top-NSEL by iterative argmax over the CAND candidates
    for (int it = 0; it < NSEL; it++) {
        float bv = -FLT_MAX_; int bp = 0;
        if (tid < CAND) { bv = sv[tid]; bp = tid; }
        #pragma unroll
        for (int o = 16; o; o >>= 1) {
            float ov = __shfl_down_sync(0xffffffffu, bv, o);
            int   op = __shfl_down_sync(0xffffffffu, bp, o);
            if (ov > bv) { bv = ov; bp = op; }
        }
        if (lane == 0) { red_v[wid] = bv; red_p[wid] = bp; }
        __syncthreads();
        if (tid == 0) {
            float m = red_v[0]; int p = red_p[0];
            #pragma unroll
            for (int w = 1; w < 8; w++) if (red_v[w] > m) { m = red_v[w]; p = red_p[w]; }
            sidx[it] = si[p];
            sv[p] = -FLT_MAX_;
        }
        __syncthreads();
    }

    // exact fp32 rescore: s = <proj_n, emb_raw[idx]> / max(||emb_raw[idx]||, eps)
    for (int c = wid; c < NSEL; c += 8) {
        int idx = sidx[c];
        float s = 0.f, e2 = 0.f;
        if (idx >= 0) {
            const float* e = emb_raw + (size_t)idx * EDIM;
            for (int j = lane; j < EDIM; j += 32) {
                float ev = e[j];
                s  = fmaf(sh_proj[j], ev, s);
                e2 = fmaf(ev, ev, e2);
            }
        }
        #pragma unroll
        for (int o = 16; o; o >>= 1) {
            s  += __shfl_xor_sync(0xffffffffu, s, o);
            e2 += __shfl_xor_sync(0xffffffffu, e2, o);
        }
        if (lane == 0) strue[c] = (idx >= 0) ? s / fmaxf(sqrtf(e2), NORM_EPS) : -FLT_MAX_;
    }
    __syncthreads();

    if (tid == 0) {
        // stable top-8: val desc, index asc (matches lax.top_k)
        float fv[TOPK]; int fi[TOPK];
        unsigned used = 0;
        for (int r = 0; r < TOPK; r++) {
            int best = -1; float bv = 0.f; int bi = 0;
            for (int c = 0; c < NSEL; c++) {
                if ((used >> c) & 1u) continue;
                float v = strue[c]; int ix = sidx[c];
                if (best < 0 || v > bv || (v == bv && ix < bi)) { best = c; bv = v; bi = ix; }
            }
            used |= 1u << best;
            fv[r] = bv; fi[r] = bi;
        }
        // gumbel-argmax sampling (partitionable threefry, xor-fold)
        float m = -FLT_MAX_; int arg = 0;
        #pragma unroll
        for (int k = 0; k < TOPK; k++) {
            unsigned i = (unsigned)row * TOPK + k;
            unsigned bits = jax_random_bits32(i);
            float f = __uint_as_float((bits >> 9) | 0x3f800000u) - 1.0f;
            float u = fmaxf(TINY_F, f);
            float gmb = -logf(-logf(u));
            float t = fv[k] + gmb;
            if (t > m) { m = t; arg = k; }
        }
        out[row] = (float)fi[arg];
    }
}

// ---------------- launcher ----------------
extern "C" void kernel_launch(void* const* d_in, const int* in_sizes, int n_in,
                              void* d_out, int out_size) {
    int ie = 0, ip = 0;
    long b1 = -1, b2 = -1;
    for (int i = 0; i < n_in; i++) {
        long s = in_sizes[i];
        if (s > b1)      { b2 = b1; ip = ie; b1 = s; ie = i; }
        else if (s > b2) { b2 = s; ip = i; }
    }
    const float* emb  = (const float*)d_in[ie];   // [50257,512]
    const float* proj = (const float*)d_in[ip];   // [4,1024,512]
    float* out = (float*)d_out;                   // [4,1024] float32 token ids

    cudaFuncSetAttribute(gemm_topk_kernel,
                         cudaFuncAttributeMaxDynamicSharedMemorySize, SMEM_GEMM);

    normalize_kernel<<<VPAD, 128>>>(emb, V_REAL, /*which=*/0);
    normalize_kernel<<<MROWS, 128>>>(proj, MROWS, /*which=*/1);
    gemm_topk_kernel<<<dim3(GN, 32), 256, SMEM_GEMM>>>();
    merge_sample_kernel<<<MROWS, 256>>>(proj, emb, out);
}